// round 10
// baseline (speedup 1.0000x reference)
#include <cuda_runtime.h>
#include <math.h>
#include <float.h>
#include <stdint.h>

// Problem constants
#define H_   248
#define W_   216
#define HW   (H_*W_)          // 53568
#define NANCH 6
#define NTOT (HW*NANCH)       // 321408 rows per batch
#define NT4  (NTOT/4)         // 80352
#define BSZ  16
#define NPRE 100
#define MAXN 50
#define NBINS 2048
#define CAP   3072

// Scratch (static device globals; zero-initialized at load)
__device__ int g_hist[BSZ][NBINS];
__device__ int g_thr[BSZ];
__device__ int g_cnt[BSZ];
__device__ int g_ci[BSZ][CAP];    // candidate original row indices i = s*6 + a

__device__ __forceinline__ unsigned fkey(float v) {
    unsigned b = __float_as_uint(v);
    return (b & 0x80000000u) ? ~b : (b | 0x80000000u); // monotone float->uint
}

__device__ __forceinline__ void maxlogit4(const float* __restrict__ cls,
                                          int b, int j4, float4* out) {
    int j = j4 * 4;
    int a = j / HW, s = j - a * HW;           // 4-group never crosses 'a' (HW%4==0)
    const float4* base = (const float4*)(cls + (size_t)b * 18 * HW + (size_t)(3 * a) * HW + s);
    float4 v0 = base[0];
    float4 v1 = base[HW / 4];
    float4 v2 = base[2 * (HW / 4)];
    out->x = fmaxf(v0.x, fmaxf(v1.x, v2.x));
    out->y = fmaxf(v0.y, fmaxf(v1.y, v2.y));
    out->z = fmaxf(v0.z, fmaxf(v1.z, v2.z));
    out->w = fmaxf(v0.w, fmaxf(v1.w, v2.w));
}

// ---------------------------------------------------------------------------
// Pass 1: histogram of 11-bit monotone key of max-logit (no score array write).
// Warp-aggregated shared atomics (hot bins -> heavy clustering).
__global__ void k_score(const float* __restrict__ cls) {
    __shared__ int sh[NBINS];
    for (int i = threadIdx.x; i < NBINS; i += blockDim.x) sh[i] = 0;
    __syncthreads();

    int b = blockIdx.y;
    int j4 = blockIdx.x * blockDim.x + threadIdx.x;
    bool act = (j4 < NT4);
    unsigned bins[4] = {0xFFFFFFFFu, 0xFFFFFFFFu, 0xFFFFFFFFu, 0xFFFFFFFFu};
    if (act) {
        float4 m;
        maxlogit4(cls, b, j4, &m);
        bins[0] = fkey(m.x) >> 21;
        bins[1] = fkey(m.y) >> 21;
        bins[2] = fkey(m.z) >> 21;
        bins[3] = fkey(m.w) >> 21;
    }
    int lane = threadIdx.x & 31;
    #pragma unroll
    for (int k = 0; k < 4; k++) {
        unsigned bk = bins[k];
        unsigned mask = __match_any_sync(0xFFFFFFFFu, bk);
        if (bk != 0xFFFFFFFFu && lane == (__ffs(mask) - 1))
            atomicAdd(&sh[bk], __popc(mask));
    }
    __syncthreads();
    for (int i = threadIdx.x; i < NBINS; i += blockDim.x)
        if (sh[i]) atomicAdd(&g_hist[b][i], sh[i]);
}

// Threshold bin per batch: largest t with sum_{k>=t} hist[k] >= NPRE.
// Also zeroes the histogram for the next graph replay.
__global__ void k_thresh() {
    int b = blockIdx.x, tid = threadIdx.x;  // 256 threads
    __shared__ int a[256];
    __shared__ int red[256];
    int binv[8];
    int base = tid * 8, s = 0;
    #pragma unroll
    for (int k = 0; k < 8; k++) { binv[k] = g_hist[b][base + k]; s += binv[k]; }
    a[tid] = s;
    __syncthreads();
    #pragma unroll
    for (int k = 0; k < 8; k++) g_hist[b][base + k] = 0;   // reset for replay
    // inclusive suffix sum over 256 chunk sums
    for (int off = 1; off < 256; off <<= 1) {
        int t = (tid + off < 256) ? a[tid + off] : 0;
        __syncthreads();
        a[tid] += t;
        __syncthreads();
    }
    int acc = (tid < 255) ? a[tid + 1] : 0;   // sum of chunks strictly above mine
    int best = 0;
    for (int k = 7; k >= 0; k--) {
        acc += binv[k];
        if (acc >= NPRE) { best = base + k; break; }
    }
    red[tid] = best;
    __syncthreads();
    for (int off = 128; off > 0; off >>= 1) {
        if (tid < off) red[tid] = max(red[tid], red[tid + off]);
        __syncthreads();
    }
    if (tid == 0) g_thr[b] = red[0];
}

// Collect candidate indices above threshold (recompute max from L2-resident cls)
__global__ void k_collect(const float* __restrict__ cls) {
    int b = blockIdx.y;
    unsigned t = (unsigned)g_thr[b];
    int j4 = blockIdx.x * blockDim.x + threadIdx.x;
    if (j4 >= NT4) return;
    float4 m;
    maxlogit4(cls, b, j4, &m);
    float vv[4] = {m.x, m.y, m.z, m.w};
    int j = j4 * 4;
    #pragma unroll
    for (int k = 0; k < 4; k++) {
        if ((fkey(vv[k]) >> 21) >= t) {
            int slot = atomicAdd(&g_cnt[b], 1);
            if (slot < CAP) {
                int jk = j + k;
                int a2 = jk / HW, s2 = jk - a2 * HW;
                g_ci[b][slot] = s2 * 6 + a2;   // original reshaped row index
            }
        }
    }
}

// ---------------------------------------------------------------------------
// Tail megakernel, one block per batch (384 threads):
//   phase A: rebuild exact keys for C candidates, rank -> top-100 (lax.top_k order)
//   phase B: decode 100 boxes (tid<100)
//   phase C: 3-class NMS (class c = tid/128): sort, parallel suppression
//            bit-matrix, 128-bit register greedy sweep
//   phase D: top-50 over 300 flat entries, write outputs
struct Ph1 { unsigned long long ck[CAP]; };
struct Ph2 {
    unsigned long long key[3 * NPRE];   // [c][tt] during NMS; flat during out
    int      ord[3][NPRE];
    float    kvs[3][NPRE];
    float    sx1[3][NPRE], sy1[3][NPRE], sx2[3][NPRE], sy2[3][NPRE], sar[3][NPRE];
    unsigned sup[3][NPRE][4];
    unsigned km[3][4];
};

__global__ void k_tail(const float* __restrict__ cls,
                       const float* __restrict__ box,
                       const float* __restrict__ dir,
                       const float* __restrict__ anc,
                       float* __restrict__ out) {
    int b = blockIdx.x, tid = threadIdx.x;  // 384 threads
    __shared__ union { Ph1 p1; Ph2 p2; } sh;
    __shared__ int   topi[NPRE];
    __shared__ float bb[NPRE][7];
    __shared__ float b2d[NPRE][4];
    __shared__ float area[NPRE];
    __shared__ float sc3[3][NPRE];
    __shared__ float fv[3 * NPRE];
    __shared__ int   sC;

    const float PI = 3.14159265358979323846f;

    // snapshot count, THEN reset (race-free: publish via shared + barrier)
    if (tid == 0) {
        sC = min(g_cnt[b], CAP);
        g_cnt[b] = 0;   // reset for next graph replay
    }
    __syncthreads();
    int C = sC;

    // ---- phase A: exact keys + rank-select top-100 ----
    for (int u = tid; u < C; u += 384) {
        int i = g_ci[b][u];
        int s = i / 6, a = i - 6 * s;
        const float* base = cls + (size_t)b * 18 * HW + (size_t)(3 * a) * HW + s;
        float m = fmaxf(base[0], fmaxf(base[HW], base[2 * HW]));
        sh.p1.ck[u] = ((unsigned long long)fkey(m) << 32) | (0xFFFFFFFFu - (unsigned)i);
    }
    __syncthreads();
    for (int u = tid; u < C; u += 384) {
        unsigned long long k = sh.p1.ck[u];
        int r = 0;
        for (int w = 0; w < C; w++) r += (sh.p1.ck[w] > k);
        if (r < NPRE) topi[r] = (int)(0xFFFFFFFFu - (unsigned)k);
    }
    __syncthreads();

    // ---- phase B: decode ----
    if (tid < NPRE) {
        int i = topi[tid];
        int s = i / 6, a = i - 6 * s;

        const float* cb = cls + (size_t)b * 18 * HW + s;
        #pragma unroll
        for (int c = 0; c < 3; c++) {
            float x = cb[(size_t)(3 * a + c) * HW];
            sc3[c][tid] = 0.5f * tanhf(0.5f * x) + 0.5f; // sigmoid
        }

        const float* pb = box + (size_t)b * 42 * HW + s;
        float d[7];
        #pragma unroll
        for (int j = 0; j < 7; j++) d[j] = pb[(size_t)(7 * a + j) * HW];

        const float* db = dir + (size_t)b * 12 * HW + s;
        float d0 = db[(size_t)(2 * a) * HW];
        float d1 = db[(size_t)(2 * a + 1) * HW];
        int dircls = (d1 > d0) ? 1 : 0;

        const float* ab = anc + (size_t)i * 7;
        float xa = ab[0], ya = ab[1], za = ab[2];
        float wa = ab[3], la = ab[4], ha = ab[5], ra = ab[6];

        float da = sqrtf(wa * wa + la * la);
        float x = d[0] * da + xa;
        float y = d[1] * da + ya;
        float z = d[2] * ha + za + ha * 0.5f;
        float w = wa * expf(d[3]);
        float l = la * expf(d[4]);
        float h = ha * expf(d[5]);
        z = z - h * 0.5f;
        float th0 = ra + d[6];
        float lp  = th0 - floorf(th0 / PI + 1.0f) * PI;
        float th  = lp + (1.0f - (float)dircls) * PI;

        bb[tid][0] = x; bb[tid][1] = y; bb[tid][2] = z;
        bb[tid][3] = w; bb[tid][4] = l; bb[tid][5] = h; bb[tid][6] = th;

        float x1 = x - w * 0.5f, y1 = y - l * 0.5f;
        float x2 = x + w * 0.5f, y2 = y + l * 0.5f;
        b2d[tid][0] = x1; b2d[tid][1] = y1; b2d[tid][2] = x2; b2d[tid][3] = y2;
        area[tid] = (x2 - x1) * (y2 - y1);
    }
    __syncthreads();

    // ---- phase C: per-class NMS (c = tid/128, tt = tid%128) ----
    int c = tid >> 7, tt = tid & 127;
    if (tt < 4) sh.p2.km[c][tt] = 0;
    if (tt < NPRE) {
        float s = sc3[c][tt];
        float kv = (s > 0.1f) ? s : -FLT_MAX;   // valid ? score : -inf
        sh.p2.kvs[c][tt] = kv;
        sh.p2.key[c * NPRE + tt] =
            ((unsigned long long)fkey(kv) << 32) | (0xFFFFFFFFu - (unsigned)tt);
    }
    __syncthreads();
    if (tt < NPRE) {   // stable descending rank (exact argsort semantics)
        unsigned long long k = sh.p2.key[c * NPRE + tt];
        int r = 0;
        #pragma unroll 4
        for (int u = 0; u < NPRE; u++) r += (sh.p2.key[c * NPRE + u] > k);
        sh.p2.ord[c][r] = tt;
    }
    __syncthreads();
    if (tt < NPRE) {   // gather sorted boxes, init keep bits = valid
        int p = sh.p2.ord[c][tt];
        sh.p2.sx1[c][tt] = b2d[p][0]; sh.p2.sy1[c][tt] = b2d[p][1];
        sh.p2.sx2[c][tt] = b2d[p][2]; sh.p2.sy2[c][tt] = b2d[p][3];
        sh.p2.sar[c][tt] = area[p];
        if (sh.p2.kvs[c][p] != -FLT_MAX)
            atomicOr(&sh.p2.km[c][tt >> 5], 1u << (tt & 31));
    }
    __syncthreads();
    if (tt < NPRE) {   // suppression row ii=tt vs all jj>ii, fully parallel
        float ax1 = sh.p2.sx1[c][tt], ay1 = sh.p2.sy1[c][tt];
        float ax2 = sh.p2.sx2[c][tt], ay2 = sh.p2.sy2[c][tt];
        float aa = sh.p2.sar[c][tt];
        unsigned w0 = 0, w1 = 0, w2 = 0, w3 = 0;
        for (int jj = tt + 1; jj < NPRE; jj++) {
            float x1 = fmaxf(ax1, sh.p2.sx1[c][jj]);
            float y1 = fmaxf(ay1, sh.p2.sy1[c][jj]);
            float x2 = fminf(ax2, sh.p2.sx2[c][jj]);
            float y2 = fminf(ay2, sh.p2.sy2[c][jj]);
            float inter = fmaxf(x2 - x1, 0.0f) * fmaxf(y2 - y1, 0.0f);
            float iou = inter / (aa + sh.p2.sar[c][jj] - inter + 1e-8f);
            if (iou > 0.01f) {
                unsigned bit = 1u << (jj & 31);
                if (jj < 32) w0 |= bit; else if (jj < 64) w1 |= bit;
                else if (jj < 96) w2 |= bit; else w3 |= bit;
            }
        }
        sh.p2.sup[c][tt][0] = w0; sh.p2.sup[c][tt][1] = w1;
        sh.p2.sup[c][tt][2] = w2; sh.p2.sup[c][tt][3] = w3;
    }
    __syncthreads();
    if (tt == 0) {     // greedy sweep: 128-bit register AND-NOT (3 in parallel)
        unsigned k0 = sh.p2.km[c][0], k1 = sh.p2.km[c][1];
        unsigned k2 = sh.p2.km[c][2], k3 = sh.p2.km[c][3];
        for (int ii = 0; ii < NPRE; ii++) {
            unsigned bit;
            if (ii < 32) bit = (k0 >> ii) & 1u;
            else if (ii < 64) bit = (k1 >> (ii - 32)) & 1u;
            else if (ii < 96) bit = (k2 >> (ii - 64)) & 1u;
            else bit = (k3 >> (ii - 96)) & 1u;
            if (bit) {
                k0 &= ~sh.p2.sup[c][ii][0]; k1 &= ~sh.p2.sup[c][ii][1];
                k2 &= ~sh.p2.sup[c][ii][2]; k3 &= ~sh.p2.sup[c][ii][3];
            }
        }
        sh.p2.km[c][0] = k0; sh.p2.km[c][1] = k1;
        sh.p2.km[c][2] = k2; sh.p2.km[c][3] = k3;
    }
    __syncthreads();
    if (tt < NPRE) {   // fv[p] = keep ? score : -1 (keep includes valid)
        int p = sh.p2.ord[c][tt];
        unsigned bit = (sh.p2.km[c][tt >> 5] >> (tt & 31)) & 1u;
        fv[c * NPRE + p] = bit ? sc3[c][p] : -1.0f;
    }
    __syncthreads();

    // ---- phase D: top-50 over 300 flat entries, exact lax.top_k order ----
    if (tid < 3 * NPRE)
        sh.p2.key[tid] =
            ((unsigned long long)fkey(fv[tid]) << 32) | (0xFFFFFFFFu - (unsigned)tid);
    __syncthreads();
    if (tid < 3 * NPRE) {
        unsigned long long k = sh.p2.key[tid];
        int r = 0;
        #pragma unroll 4
        for (int u = 0; u < 3 * NPRE; u++) r += (sh.p2.key[u] > k);
        if (r < MAXN) {
            int sel = tid % NPRE;
            int lab = tid / NPRE;
            float v = fv[tid];
            float* ob = out + (size_t)b * MAXN * 7 + (size_t)r * 7;
            #pragma unroll
            for (int j = 0; j < 7; j++) ob[j] = bb[sel][j];
            out[BSZ * MAXN * 7 +                  b * MAXN + r] = (float)lab;
            out[BSZ * MAXN * 7 + BSZ * MAXN +     b * MAXN + r] = v;
            out[BSZ * MAXN * 7 + 2 * BSZ * MAXN + b * MAXN + r] = (v > 0.0f) ? 1.0f : 0.0f;
        }
    }
}

// ---------------------------------------------------------------------------
extern "C" void kernel_launch(void* const* d_in, const int* in_sizes, int n_in,
                              void* d_out, int out_size) {
    const float* cls = (const float*)d_in[0]; // (16,18,248,216)
    const float* box = (const float*)d_in[1]; // (16,42,248,216)
    const float* dir = (const float*)d_in[2]; // (16,12,248,216)
    const float* anc = (const float*)d_in[3]; // (248,216,3,2,7)
    float* out = (float*)d_out;

    dim3 g1((NT4 + 255) / 256, BSZ);
    k_score<<<g1, 256>>>(cls);

    k_thresh<<<BSZ, 256>>>();

    k_collect<<<g1, 256>>>(cls);

    k_tail<<<BSZ, 384>>>(cls, box, dir, anc, out);
}